// round 5
// baseline (speedup 1.0000x reference)
#include <cuda_runtime.h>
#include <cuda_fp16.h>
#include <cstdint>

#define BS   8
#define SEQ  2048
#define DIM  512
#define MQ   128
#define NK   32
#define DV   256
#define NQT  (SEQ/MQ)   // 16
#define NKT  (SEQ/NK)   // 64

__device__ __half g_Qh[(size_t)BS*SEQ*DIM];
__device__ __half g_Kh[(size_t)BS*SEQ*DIM];
__device__ __half g_Vh[(size_t)BS*SEQ*DIM];

// smem layout (bytes)
#define SM_Q   0
#define SM_K   131072            // single buffer, 32 KB
#define SM_V   (131072 + 32768)  // 2 x 16 KB
#define VBUF   16384
#define SM_SX  (SM_V + 2*VBUF)   // S-exchange: 2*8*32*64 = 32 KB
#define SM_TOTAL (SM_SX + 32768) // 229376

__device__ __forceinline__ uint32_t smem_u32(const void* p) {
    uint32_t a;
    asm("{ .reg .u64 t; cvta.to.shared.u64 t, %1; cvt.u32.u64 %0, t; }" : "=r"(a) : "l"(p));
    return a;
}
// K-major SW128 blocked atoms: atom = 8 rows x 64 halfs (1024B).
__device__ __forceinline__ uint32_t km_off(int row, int col, int natomrows) {
    uint32_t off = ((uint32_t)((col >> 6) * natomrows + (row >> 3)) << 10)
                 + ((uint32_t)(row & 7) << 7) + ((uint32_t)(col & 63) << 1);
    return off ^ ((off >> 3) & 0x70u);
}
__device__ __forceinline__ float ex2f(float x) {
    float y;
    asm("ex2.approx.f32 %0, %1;" : "=f"(y) : "f"(x));
    return y;
}
__device__ __forceinline__ void cp16(uint32_t dst, const void* src) {
    asm volatile("cp.async.cg.shared.global [%0], [%1], 16;" :: "r"(dst), "l"(src));
}
#define CP_COMMIT() asm volatile("cp.async.commit_group;" ::: "memory")
#define CP_WAIT1()  asm volatile("cp.async.wait_group 1;" ::: "memory")

__device__ __forceinline__ void ldsm_x4(uint32_t* r, uint32_t addr) {
    asm volatile("ldmatrix.sync.aligned.m8n8.x4.shared.b16 {%0,%1,%2,%3}, [%4];"
        : "=r"(r[0]), "=r"(r[1]), "=r"(r[2]), "=r"(r[3]) : "r"(addr));
}
__device__ __forceinline__ void ldsm_x4t(uint32_t* r, uint32_t addr) {
    asm volatile("ldmatrix.sync.aligned.m8n8.x4.trans.shared.b16 {%0,%1,%2,%3}, [%4];"
        : "=r"(r[0]), "=r"(r[1]), "=r"(r[2]), "=r"(r[3]) : "r"(addr));
}
__device__ __forceinline__ void mma16816(float* c, const uint32_t* a, const uint32_t* b) {
    asm volatile("mma.sync.aligned.m16n8k16.row.col.f32.f16.f16.f32 "
        "{%0,%1,%2,%3}, {%4,%5,%6,%7}, {%8,%9}, {%0,%1,%2,%3};"
        : "+f"(c[0]), "+f"(c[1]), "+f"(c[2]), "+f"(c[3])
        : "r"(a[0]), "r"(a[1]), "r"(a[2]), "r"(a[3]), "r"(b[0]), "r"(b[1]));
}

__global__ void convert_kernel(const float* __restrict__ q, const float* __restrict__ k,
                               const float* __restrict__ v, int n4) {
    int i = blockIdx.x * blockDim.x + threadIdx.x;
    if (i >= n4) return;
    float4 a = reinterpret_cast<const float4*>(q)[i];
    float4 b = reinterpret_cast<const float4*>(k)[i];
    float4 c = reinterpret_cast<const float4*>(v)[i];
    __half2 h;
    uint2 u;
    h = __floats2half2_rn(a.x, a.y); u.x = *reinterpret_cast<uint32_t*>(&h);
    h = __floats2half2_rn(a.z, a.w); u.y = *reinterpret_cast<uint32_t*>(&h);
    reinterpret_cast<uint2*>(g_Qh)[i] = u;
    h = __floats2half2_rn(b.x, b.y); u.x = *reinterpret_cast<uint32_t*>(&h);
    h = __floats2half2_rn(b.z, b.w); u.y = *reinterpret_cast<uint32_t*>(&h);
    reinterpret_cast<uint2*>(g_Kh)[i] = u;
    h = __floats2half2_rn(c.x, c.y); u.x = *reinterpret_cast<uint32_t*>(&h);
    h = __floats2half2_rn(c.z, c.w); u.y = *reinterpret_cast<uint32_t*>(&h);
    reinterpret_cast<uint2*>(g_Vh)[i] = u;
}

__device__ __forceinline__ void load_k(const __half* Kg, int tid, uint32_t kbuf) {
    #pragma unroll
    for (int i = tid; i < NK * (DIM / 8); i += 512) {   // 4 per thread
        int r = i >> 6, c8 = i & 63;
        cp16(kbuf + km_off(r, c8 * 8, NK / 8), Kg + (size_t)r * DIM + c8 * 8);
    }
}
__device__ __forceinline__ void load_v(const __half* Vg, int tid, uint32_t vbuf) {
    #pragma unroll
    for (int i = tid; i < NK * (DV / 8); i += 512) {    // 2 per thread
        int r = i >> 5, c8 = i & 31;
        cp16(vbuf + km_off(r, c8 * 8, NK / 8), Vg + (size_t)r * DIM + c8 * 8);
    }
}

// FlashAttention-2, 16 warps: pairs (wm 0..7, wk 0..1).
// QK: d-split (wk owns d-half, partial S exchanged via smem).
// PV/O: n-split (wk owns 128 of 256 output cols).
__global__ void __launch_bounds__(512, 1)
attn_kernel(const int* __restrict__ um_p, const int* __restrict__ cd_p,
            float* __restrict__ out) {
    extern __shared__ char smem[];
    const uint32_t sb = smem_u32(smem);
    const int tid = threadIdx.x, lane = tid & 31, w = tid >> 5;
    const int wm = w >> 1, wk = w & 1;
    const int qi = (NQT - 1) - blockIdx.x;       // heavy tiles first
    const int b = blockIdx.y, ds = blockIdx.z;
    const int q0 = qi * MQ, dofs = ds * DV;
    const int um = um_p[0];
    const float cl2 = 1.4426950408889634f * rsqrtf((float)cd_p[0]);
    const int nkt = um ? (4 * qi + 4) : NKT;
    const float NEG = __int_as_float(0xff800000);

    const __half* Kg0 = g_Kh + ((size_t)(b * SEQ)) * DIM;
    const __half* Vg0 = g_Vh + ((size_t)(b * SEQ)) * DIM + dofs;

    // ---- prologue: Q + K0 + V0 (group), V1 (group) ----
    {
        const __half* Qg = g_Qh + ((size_t)(b * SEQ + q0)) * DIM;
        #pragma unroll 8
        for (int i = tid; i < MQ * (DIM / 8); i += 512) {
            int r = i >> 6, c8 = i & 63;
            cp16(sb + SM_Q + km_off(r, c8 * 8, 16), Qg + (size_t)r * DIM + c8 * 8);
        }
    }
    load_k(Kg0, tid, sb + SM_K);
    load_v(Vg0, tid, sb + SM_V);
    CP_COMMIT();
    load_v(Vg0 + (size_t)NK * DIM, tid, sb + SM_V + VBUF);
    CP_COMMIT();

    float o[16][4];
    #pragma unroll
    for (int j = 0; j < 16; j++) { o[j][0] = 0.f; o[j][1] = 0.f; o[j][2] = 0.f; o[j][3] = 0.f; }
    float m0 = NEG, m1 = NEG, l0 = 0.f, l1 = 0.f;

    const int qrow0 = q0 + wm * 16 + (lane >> 2);
    const int qrow1 = qrow0 + 8;
    const int arow = wm * 16 + (lane & 15);
    const int acol = (lane >> 4) << 3;
    const int brow = lane & 7;
    const int bcol = ((lane >> 3) & 3) << 3;
    const int vrow = lane & 15;
    const int vcol = (lane >> 4) << 3;
    const int dbase = wk * 256;                  // d-half for QK
    // S-exchange slots (64B per thread), float4-rotated to avoid bank conflicts
    const uint32_t sx_own = sb + SM_SX + (uint32_t)(((wk * 8 + wm) * 32 + lane) * 64);
    const uint32_t sx_par = sb + SM_SX + (uint32_t)((((1 - wk) * 8 + wm) * 32 + lane) * 64);
    const int r4 = (lane >> 1) & 3;

    for (int kt = 0; kt < nkt; kt++) {
        const int k0 = kt * NK;
        const uint32_t vb = sb + SM_V + (kt & 1) * VBUF;

        CP_WAIT1();              // K[kt] (and V[kt]) landed
        __syncthreads();

        // ---- partial S = Q K^T over d-half [dbase, dbase+256) ----
        float s[4][4];
        #pragma unroll
        for (int nt = 0; nt < 4; nt++) { s[nt][0] = 0.f; s[nt][1] = 0.f; s[nt][2] = 0.f; s[nt][3] = 0.f; }
        #pragma unroll
        for (int kc2 = 0; kc2 < 8; kc2++) {
            const int dc = dbase + kc2 * 32;
            uint32_t a0[4], a1[4];
            ldsm_x4(a0, sb + SM_Q + km_off(arow, dc + acol, 16));
            ldsm_x4(a1, sb + SM_Q + km_off(arow, dc + 16 + acol, 16));
            #pragma unroll
            for (int nt = 0; nt < 4; nt++) {
                uint32_t bb[4];
                ldsm_x4(bb, sb + SM_K + km_off(nt * 8 + brow, dc + bcol, NK / 8));
                mma16816(s[nt], a0, bb);
                mma16816(s[nt], a1, bb + 2);
            }
        }

        // ---- exchange partial S with partner warp (other d-half) ----
        #pragma unroll
        for (int nt = 0; nt < 4; nt++) {
            int slot = (nt + r4) & 3;
            *reinterpret_cast<float4*>(smem + (sx_own - sb) + slot * 16) =
                make_float4(s[nt][0], s[nt][1], s[nt][2], s[nt][3]);
        }
        __syncthreads();
        // K[kt] fully consumed -> prefetch K[kt+1] into the single K buffer
        if (kt + 1 < nkt) load_k(Kg0 + (size_t)(k0 + NK) * DIM, tid, sb + SM_K);
        CP_COMMIT();
        #pragma unroll
        for (int nt = 0; nt < 4; nt++) {
            int slot = (nt + r4) & 3;
            float4 p = *reinterpret_cast<const float4*>(smem + (sx_par - sb) + slot * 16);
            s[nt][0] += p.x; s[nt][1] += p.y; s[nt][2] += p.z; s[nt][3] += p.w;
        }

        // ---- causal mask (diagonal tiles only) ----
        if (um && kt >= 4 * qi) {
            #pragma unroll
            for (int nt = 0; nt < 4; nt++) {
                int c = k0 + nt * 8 + ((lane & 3) << 1);
                if (c     > qrow0) s[nt][0] = NEG;
                if (c + 1 > qrow0) s[nt][1] = NEG;
                if (c     > qrow1) s[nt][2] = NEG;
                if (c + 1 > qrow1) s[nt][3] = NEG;
            }
        }

        // ---- online softmax (full 32 keys; duplicated across wk pair) ----
        float vx0 = NEG, vx1 = NEG;
        #pragma unroll
        for (int nt = 0; nt < 4; nt++) {
            vx0 = fmaxf(vx0, fmaxf(s[nt][0], s[nt][1]));
            vx1 = fmaxf(vx1, fmaxf(s[nt][2], s[nt][3]));
        }
        vx0 = fmaxf(vx0, __shfl_xor_sync(0xffffffffu, vx0, 1));
        vx0 = fmaxf(vx0, __shfl_xor_sync(0xffffffffu, vx0, 2));
        vx1 = fmaxf(vx1, __shfl_xor_sync(0xffffffffu, vx1, 1));
        vx1 = fmaxf(vx1, __shfl_xor_sync(0xffffffffu, vx1, 2));
        const float nm0 = fmaxf(m0, vx0), nm1 = fmaxf(m1, vx1);

        float sum0 = 0.f, sum1 = 0.f;
        #pragma unroll
        for (int nt = 0; nt < 4; nt++) {
            s[nt][0] = ex2f((s[nt][0] - nm0) * cl2);
            s[nt][1] = ex2f((s[nt][1] - nm0) * cl2);
            s[nt][2] = ex2f((s[nt][2] - nm1) * cl2);
            s[nt][3] = ex2f((s[nt][3] - nm1) * cl2);
            sum0 += s[nt][0] + s[nt][1];
            sum1 += s[nt][2] + s[nt][3];
        }
        sum0 += __shfl_xor_sync(0xffffffffu, sum0, 1);
        sum0 += __shfl_xor_sync(0xffffffffu, sum0, 2);
        sum1 += __shfl_xor_sync(0xffffffffu, sum1, 1);
        sum1 += __shfl_xor_sync(0xffffffffu, sum1, 2);

        const bool rescale = (vx0 > m0) || (vx1 > m1);
        const float al0 = ex2f((m0 - nm0) * cl2), al1 = ex2f((m1 - nm1) * cl2);
        l0 = l0 * al0 + sum0;
        l1 = l1 * al1 + sum1;
        m0 = nm0; m1 = nm1;
        if (__any_sync(0xffffffffu, rescale)) {
            #pragma unroll
            for (int j = 0; j < 16; j++) {
                o[j][0] *= al0; o[j][1] *= al0; o[j][2] *= al1; o[j][3] *= al1;
            }
        }

        // ---- P (f16) A-fragments directly from registers ----
        uint32_t pa[2][4];
        #pragma unroll
        for (int kc = 0; kc < 2; kc++) {
            __half2 h;
            h = __floats2half2_rn(s[2*kc][0],   s[2*kc][1]);   pa[kc][0] = *reinterpret_cast<uint32_t*>(&h);
            h = __floats2half2_rn(s[2*kc][2],   s[2*kc][3]);   pa[kc][1] = *reinterpret_cast<uint32_t*>(&h);
            h = __floats2half2_rn(s[2*kc+1][0], s[2*kc+1][1]); pa[kc][2] = *reinterpret_cast<uint32_t*>(&h);
            h = __floats2half2_rn(s[2*kc+1][2], s[2*kc+1][3]); pa[kc][3] = *reinterpret_cast<uint32_t*>(&h);
        }

        // ---- O += P V  (own 128-col half) ----
        #pragma unroll
        for (int dt2 = 0; dt2 < 8; dt2++) {
            const int dc = wk * 128 + dt2 * 16;
            #pragma unroll
            for (int kc = 0; kc < 2; kc++) {
                uint32_t bb[4];
                ldsm_x4t(bb, vb + km_off(kc * 16 + vrow, dc + vcol, NK / 8));
                mma16816(o[2*dt2],     pa[kc], bb);
                mma16816(o[2*dt2 + 1], pa[kc], bb + 2);
            }
        }

        // ---- V[kt+2] into the consumed V buffer ----
        __syncthreads();
        if (kt + 2 < nkt) load_v(Vg0 + (size_t)(k0 + 2 * NK) * DIM, tid, vb);
        CP_COMMIT();
    }

    // ---- epilogue ----
    const float i0 = 1.f / l0, i1 = 1.f / l1;
    float* out0 = out + ((size_t)b * SEQ + qrow0) * DIM + dofs + wk * 128;
    float* out1 = out + ((size_t)b * SEQ + qrow1) * DIM + dofs + wk * 128;
    const int cofs = (lane & 3) << 1;
    #pragma unroll
    for (int j = 0; j < 16; j++) {
        float2 v0 = make_float2(o[j][0] * i0, o[j][1] * i0);
        float2 v1 = make_float2(o[j][2] * i1, o[j][3] * i1);
        *reinterpret_cast<float2*>(out0 + j * 8 + cofs) = v0;
        *reinterpret_cast<float2*>(out1 + j * 8 + cofs) = v1;
    }
}

extern "C" void kernel_launch(void* const* d_in, const int* in_sizes, int n_in,
                              void* d_out, int out_size) {
    const float* Q = (const float*)d_in[0];
    const float* K = (const float*)d_in[1];
    const float* V = (const float*)d_in[2];
    const int* use_mask = (const int*)d_in[3];
    const int* cell_dim = (const int*)d_in[4];
    float* out = (float*)d_out;

    int n4 = (BS * SEQ * DIM) / 4;
    convert_kernel<<<(n4 + 255) / 256, 256>>>(Q, K, V, n4);

    cudaFuncSetAttribute(attn_kernel, cudaFuncAttributeMaxDynamicSharedMemorySize, SM_TOTAL);
    attn_kernel<<<dim3(NQT, BS, 2), 512, SM_TOTAL>>>(use_mask, cell_dim, out);
}

// round 6
// speedup vs baseline: 2.1549x; 2.1549x over previous
#include <cuda_runtime.h>
#include <cuda_fp16.h>
#include <cstdint>

#define BS   8
#define SEQ  2048
#define DIM  512
#define MQ   128
#define NK   32
#define DV   256
#define NQT  (SEQ/MQ)   // 16
#define NKT  (SEQ/NK)   // 64

__device__ __half g_Qh[(size_t)BS*SEQ*DIM];
__device__ __half g_Kh[(size_t)BS*SEQ*DIM];
__device__ __half g_Vh[(size_t)BS*SEQ*DIM];

#define SM_Q   0
#define SM_K   131072
#define SM_V   (131072 + 65536)
#define KBUF   32768
#define VBUF   16384
#define SM_TOTAL (SM_V + 2*VBUF)   // 229376 bytes

__device__ __forceinline__ uint32_t smem_u32(const void* p) {
    uint32_t a;
    asm("{ .reg .u64 t; cvta.to.shared.u64 t, %1; cvt.u32.u64 %0, t; }" : "=r"(a) : "l"(p));
    return a;
}
// K-major SW128 blocked atoms: atom = 8 rows x 64 halfs (1024B).
__device__ __forceinline__ uint32_t km_off(int row, int col, int natomrows) {
    uint32_t off = ((uint32_t)((col >> 6) * natomrows + (row >> 3)) << 10)
                 + ((uint32_t)(row & 7) << 7) + ((uint32_t)(col & 63) << 1);
    return off ^ ((off >> 3) & 0x70u);
}
__device__ __forceinline__ float ex2f(float x) {
    float y;
    asm("ex2.approx.f32 %0, %1;" : "=f"(y) : "f"(x));
    return y;
}
__device__ __forceinline__ void cp16(uint32_t dst, const void* src) {
    asm volatile("cp.async.cg.shared.global [%0], [%1], 16;" :: "r"(dst), "l"(src));
}
#define CP_COMMIT() asm volatile("cp.async.commit_group;" ::: "memory")
#define CP_WAIT1()  asm volatile("cp.async.wait_group 1;" ::: "memory")
#define CP_WAIT0()  asm volatile("cp.async.wait_group 0;" ::: "memory")

__device__ __forceinline__ void ldsm_x4(uint32_t* r, uint32_t addr) {
    asm volatile("ldmatrix.sync.aligned.m8n8.x4.shared.b16 {%0,%1,%2,%3}, [%4];"
        : "=r"(r[0]), "=r"(r[1]), "=r"(r[2]), "=r"(r[3]) : "r"(addr));
}
__device__ __forceinline__ void ldsm_x4t(uint32_t* r, uint32_t addr) {
    asm volatile("ldmatrix.sync.aligned.m8n8.x4.trans.shared.b16 {%0,%1,%2,%3}, [%4];"
        : "=r"(r[0]), "=r"(r[1]), "=r"(r[2]), "=r"(r[3]) : "r"(addr));
}
__device__ __forceinline__ void mma16816(float* c, const uint32_t* a, const uint32_t* b) {
    asm volatile("mma.sync.aligned.m16n8k16.row.col.f32.f16.f16.f32 "
        "{%0,%1,%2,%3}, {%4,%5,%6,%7}, {%8,%9}, {%0,%1,%2,%3};"
        : "+f"(c[0]), "+f"(c[1]), "+f"(c[2]), "+f"(c[3])
        : "r"(a[0]), "r"(a[1]), "r"(a[2]), "r"(a[3]), "r"(b[0]), "r"(b[1]));
}

__global__ void convert_kernel(const float* __restrict__ q, const float* __restrict__ k,
                               const float* __restrict__ v, int n4) {
    int i = blockIdx.x * blockDim.x + threadIdx.x;
    if (i >= n4) return;
    float4 a = reinterpret_cast<const float4*>(q)[i];
    float4 b = reinterpret_cast<const float4*>(k)[i];
    float4 c = reinterpret_cast<const float4*>(v)[i];
    __half2 h;
    uint2 u;
    h = __floats2half2_rn(a.x, a.y); u.x = *reinterpret_cast<uint32_t*>(&h);
    h = __floats2half2_rn(a.z, a.w); u.y = *reinterpret_cast<uint32_t*>(&h);
    reinterpret_cast<uint2*>(g_Qh)[i] = u;
    h = __floats2half2_rn(b.x, b.y); u.x = *reinterpret_cast<uint32_t*>(&h);
    h = __floats2half2_rn(b.z, b.w); u.y = *reinterpret_cast<uint32_t*>(&h);
    reinterpret_cast<uint2*>(g_Kh)[i] = u;
    h = __floats2half2_rn(c.x, c.y); u.x = *reinterpret_cast<uint32_t*>(&h);
    h = __floats2half2_rn(c.z, c.w); u.y = *reinterpret_cast<uint32_t*>(&h);
    reinterpret_cast<uint2*>(g_Vh)[i] = u;
}

__device__ __forceinline__ void load_kv(const __half* Kg, const __half* Vg, int tid,
                                        uint32_t kbuf, uint32_t vbuf) {
    #pragma unroll
    for (int i = tid; i < NK * (DIM / 8); i += 256) {
        int r = i >> 6, c8 = i & 63;
        cp16(kbuf + km_off(r, c8 * 8, NK / 8), Kg + (size_t)r * DIM + c8 * 8);
    }
    #pragma unroll
    for (int i = tid; i < NK * (DV / 8); i += 256) {
        int r = i >> 5, c8 = i & 31;
        cp16(vbuf + km_off(r, c8 * 8, NK / 8), Vg + (size_t)r * DIM + c8 * 8);
    }
}

// FlashAttention-2, mma.sync.m16n8k16, 8 warps m-split, double-buffered K/V.
// grid (8, BS, 2): each CTA processes q-tile pair {15-x, x} -> constant 68 iters/CTA.
__global__ void __launch_bounds__(256, 1)
attn_kernel(const int* __restrict__ um_p, const int* __restrict__ cd_p,
            float* __restrict__ out) {
    extern __shared__ char smem[];
    const uint32_t sb = smem_u32(smem);
    const int tid = threadIdx.x, lane = tid & 31, w = tid >> 5;
    const int b = blockIdx.y, ds = blockIdx.z;
    const int dofs = ds * DV;
    const int um = um_p[0];
    const float cl2 = 1.4426950408889634f * rsqrtf((float)cd_p[0]);
    const float NEG = __int_as_float(0xff800000);

    const __half* Kg0 = g_Kh + ((size_t)(b * SEQ)) * DIM;
    const __half* Vg0 = g_Vh + ((size_t)(b * SEQ)) * DIM + dofs;

    const int arow = w * 16 + (lane & 15);
    const int acol = (lane >> 4) << 3;
    const int brow = lane & 7;
    const int bcol = ((lane >> 3) & 3) << 3;
    const int vrow = lane & 15;
    const int vcol = (lane >> 4) << 3;
    const int cofs = (lane & 3) << 1;

    #pragma unroll 1
    for (int ph = 0; ph < 2; ph++) {
        const int qi = ph ? (int)blockIdx.x : (NQT - 1) - (int)blockIdx.x; // heavy first
        const int q0 = qi * MQ;
        const int nkt = um ? (4 * qi + 4) : NKT;

        // ---- phase prologue: Q tile + KV0 (group), KV1 (group) ----
        CP_WAIT0();            // make sure smem is no longer a cp.async target from prev phase
        __syncthreads();
        {
            const __half* Qg = g_Qh + ((size_t)(b * SEQ + q0)) * DIM;
            #pragma unroll 8
            for (int i = tid; i < MQ * (DIM / 8); i += 256) {
                int r = i >> 6, c8 = i & 63;
                cp16(sb + SM_Q + km_off(r, c8 * 8, 16), Qg + (size_t)r * DIM + c8 * 8);
            }
        }
        load_kv(Kg0, Vg0, tid, sb + SM_K, sb + SM_V);
        CP_COMMIT();
        load_kv(Kg0 + (size_t)NK * DIM, Vg0 + (size_t)NK * DIM, tid,
                sb + SM_K + KBUF, sb + SM_V + VBUF);
        CP_COMMIT();

        float o[32][4];
        #pragma unroll
        for (int j = 0; j < 32; j++) { o[j][0] = 0.f; o[j][1] = 0.f; o[j][2] = 0.f; o[j][3] = 0.f; }
        float m0 = NEG, m1 = NEG, l0 = 0.f, l1 = 0.f;

        const int qrow0 = q0 + w * 16 + (lane >> 2);
        const int qrow1 = qrow0 + 8;

        for (int kt = 0; kt < nkt; kt++) {
            const int k0 = kt * NK;
            const uint32_t kb = sb + SM_K + (kt & 1) * KBUF;
            const uint32_t vb = sb + SM_V + (kt & 1) * VBUF;

            CP_WAIT1();
            __syncthreads();

            // ---- S = Q K^T ----
            float s[4][4];
            #pragma unroll
            for (int nt = 0; nt < 4; nt++) { s[nt][0] = 0.f; s[nt][1] = 0.f; s[nt][2] = 0.f; s[nt][3] = 0.f; }
            #pragma unroll
            for (int kc2 = 0; kc2 < 16; kc2++) {
                uint32_t a0[4], a1[4];
                ldsm_x4(a0, sb + SM_Q + km_off(arow, kc2 * 32 + acol, 16));
                ldsm_x4(a1, sb + SM_Q + km_off(arow, kc2 * 32 + 16 + acol, 16));
                #pragma unroll
                for (int nt = 0; nt < 4; nt++) {
                    uint32_t bb[4];
                    ldsm_x4(bb, kb + km_off(nt * 8 + brow, kc2 * 32 + bcol, NK / 8));
                    mma16816(s[nt], a0, bb);
                    mma16816(s[nt], a1, bb + 2);
                }
            }

            // ---- causal mask (diagonal tiles only) ----
            if (um && kt >= 4 * qi) {
                #pragma unroll
                for (int nt = 0; nt < 4; nt++) {
                    int c = k0 + nt * 8 + cofs;
                    if (c     > qrow0) s[nt][0] = NEG;
                    if (c + 1 > qrow0) s[nt][1] = NEG;
                    if (c     > qrow1) s[nt][2] = NEG;
                    if (c + 1 > qrow1) s[nt][3] = NEG;
                }
            }

            // ---- online softmax ----
            float vx0 = NEG, vx1 = NEG;
            #pragma unroll
            for (int nt = 0; nt < 4; nt++) {
                vx0 = fmaxf(vx0, fmaxf(s[nt][0], s[nt][1]));
                vx1 = fmaxf(vx1, fmaxf(s[nt][2], s[nt][3]));
            }
            vx0 = fmaxf(vx0, __shfl_xor_sync(0xffffffffu, vx0, 1));
            vx0 = fmaxf(vx0, __shfl_xor_sync(0xffffffffu, vx0, 2));
            vx1 = fmaxf(vx1, __shfl_xor_sync(0xffffffffu, vx1, 1));
            vx1 = fmaxf(vx1, __shfl_xor_sync(0xffffffffu, vx1, 2));
            const float nm0 = fmaxf(m0, vx0), nm1 = fmaxf(m1, vx1);

            float sum0 = 0.f, sum1 = 0.f;
            #pragma unroll
            for (int nt = 0; nt < 4; nt++) {
                s[nt][0] = ex2f((s[nt][0] - nm0) * cl2);
                s[nt][1] = ex2f((s[nt][1] - nm0) * cl2);
                s[nt][2] = ex2f((s[nt][2] - nm1) * cl2);
                s[nt][3] = ex2f((s[nt][3] - nm1) * cl2);
                sum0 += s[nt][0] + s[nt][1];
                sum1 += s[nt][2] + s[nt][3];
            }
            sum0 += __shfl_xor_sync(0xffffffffu, sum0, 1);
            sum0 += __shfl_xor_sync(0xffffffffu, sum0, 2);
            sum1 += __shfl_xor_sync(0xffffffffu, sum1, 1);
            sum1 += __shfl_xor_sync(0xffffffffu, sum1, 2);

            const bool rescale = (vx0 > m0) || (vx1 > m1);
            const float al0 = ex2f((m0 - nm0) * cl2), al1 = ex2f((m1 - nm1) * cl2);
            l0 = l0 * al0 + sum0;
            l1 = l1 * al1 + sum1;
            m0 = nm0; m1 = nm1;
            if (__any_sync(0xffffffffu, rescale)) {
                #pragma unroll
                for (int j = 0; j < 32; j++) {
                    o[j][0] *= al0; o[j][1] *= al0; o[j][2] *= al1; o[j][3] *= al1;
                }
            }

            // ---- P (f16) A-fragments from registers ----
            uint32_t pa[2][4];
            #pragma unroll
            for (int kc = 0; kc < 2; kc++) {
                __half2 h;
                h = __floats2half2_rn(s[2*kc][0],   s[2*kc][1]);   pa[kc][0] = *reinterpret_cast<uint32_t*>(&h);
                h = __floats2half2_rn(s[2*kc][2],   s[2*kc][3]);   pa[kc][1] = *reinterpret_cast<uint32_t*>(&h);
                h = __floats2half2_rn(s[2*kc+1][0], s[2*kc+1][1]); pa[kc][2] = *reinterpret_cast<uint32_t*>(&h);
                h = __floats2half2_rn(s[2*kc+1][2], s[2*kc+1][3]); pa[kc][3] = *reinterpret_cast<uint32_t*>(&h);
            }

            // ---- O += P V ----
            #pragma unroll
            for (int dt2 = 0; dt2 < 16; dt2++) {
                #pragma unroll
                for (int kc = 0; kc < 2; kc++) {
                    uint32_t bb[4];
                    ldsm_x4t(bb, vb + km_off(kc * 16 + vrow, dt2 * 16 + vcol, NK / 8));
                    mma16816(o[2*dt2],     pa[kc], bb);
                    mma16816(o[2*dt2 + 1], pa[kc], bb + 2);
                }
            }

            // ---- prefetch tile kt+2 into just-consumed buffers ----
            __syncthreads();
            if (kt + 2 < nkt) {
                load_kv(Kg0 + (size_t)(k0 + 2 * NK) * DIM, Vg0 + (size_t)(k0 + 2 * NK) * DIM,
                        tid, kb, vb);
            }
            CP_COMMIT();
        }

        // ---- phase epilogue ----
        const float i0 = 1.f / l0, i1 = 1.f / l1;
        float* out0 = out + ((size_t)b * SEQ + qrow0) * DIM + dofs;
        float* out1 = out + ((size_t)b * SEQ + qrow1) * DIM + dofs;
        #pragma unroll
        for (int j = 0; j < 32; j++) {
            float2 v0 = make_float2(o[j][0] * i0, o[j][1] * i0);
            float2 v1 = make_float2(o[j][2] * i1, o[j][3] * i1);
            *reinterpret_cast<float2*>(out0 + j * 8 + cofs) = v0;
            *reinterpret_cast<float2*>(out1 + j * 8 + cofs) = v1;
        }
    }
}

extern "C" void kernel_launch(void* const* d_in, const int* in_sizes, int n_in,
                              void* d_out, int out_size) {
    const float* Q = (const float*)d_in[0];
    const float* K = (const float*)d_in[1];
    const float* V = (const float*)d_in[2];
    const int* use_mask = (const int*)d_in[3];
    const int* cell_dim = (const int*)d_in[4];
    float* out = (float*)d_out;

    int n4 = (BS * SEQ * DIM) / 4;
    convert_kernel<<<(n4 + 255) / 256, 256>>>(Q, K, V, n4);

    cudaFuncSetAttribute(attn_kernel, cudaFuncAttributeMaxDynamicSharedMemorySize, SM_TOTAL);
    attn_kernel<<<dim3(NQT / 2, BS, 2), 256, SM_TOTAL>>>(use_mask, cell_dim, out);
}

// round 7
// speedup vs baseline: 2.3914x; 1.1097x over previous
#include <cuda_runtime.h>
#include <cuda_fp16.h>
#include <cstdint>

#define BS   8
#define SEQ  2048
#define DIM  512
#define MQ   128
#define NKK  64                 // keys per macro-iteration
#define DV   256
#define NQT  (SEQ/MQ)           // 16
#define NKT  (SEQ/NKK)          // 32

__device__ __half g_Qh[(size_t)BS*SEQ*DIM];
__device__ __half g_Kh[(size_t)BS*SEQ*DIM];
__device__ __half g_Vh[(size_t)BS*SEQ*DIM];

#define SM_Q   0
#define SM_K   131072
#define KBUF   32768            // 32 keys x 512 cols f16
#define SM_V   (131072 + 65536)
#define VBUF   16384            // 32 keys x 256 cols f16
#define SM_TOTAL (SM_V + 2*VBUF)   // 229376 bytes

__device__ __forceinline__ uint32_t smem_u32(const void* p) {
    uint32_t a;
    asm("{ .reg .u64 t; cvta.to.shared.u64 t, %1; cvt.u32.u64 %0, t; }" : "=r"(a) : "l"(p));
    return a;
}
// K-major SW128 blocked atoms: atom = 8 rows x 64 halfs (1024B).
__device__ __forceinline__ uint32_t km_off(int row, int col, int natomrows) {
    uint32_t off = ((uint32_t)((col >> 6) * natomrows + (row >> 3)) << 10)
                 + ((uint32_t)(row & 7) << 7) + ((uint32_t)(col & 63) << 1);
    return off ^ ((off >> 3) & 0x70u);
}
__device__ __forceinline__ float ex2f(float x) {
    float y;
    asm("ex2.approx.f32 %0, %1;" : "=f"(y) : "f"(x));
    return y;
}
__device__ __forceinline__ void cp16(uint32_t dst, const void* src) {
    asm volatile("cp.async.cg.shared.global [%0], [%1], 16;" :: "r"(dst), "l"(src));
}
#define CP_COMMIT() asm volatile("cp.async.commit_group;" ::: "memory")
#define CP_WAIT1()  asm volatile("cp.async.wait_group 1;" ::: "memory")
#define CP_WAIT0()  asm volatile("cp.async.wait_group 0;" ::: "memory")

__device__ __forceinline__ void ldsm_x4(uint32_t* r, uint32_t addr) {
    asm volatile("ldmatrix.sync.aligned.m8n8.x4.shared.b16 {%0,%1,%2,%3}, [%4];"
        : "=r"(r[0]), "=r"(r[1]), "=r"(r[2]), "=r"(r[3]) : "r"(addr));
}
__device__ __forceinline__ void ldsm_x4t(uint32_t* r, uint32_t addr) {
    asm volatile("ldmatrix.sync.aligned.m8n8.x4.trans.shared.b16 {%0,%1,%2,%3}, [%4];"
        : "=r"(r[0]), "=r"(r[1]), "=r"(r[2]), "=r"(r[3]) : "r"(addr));
}
__device__ __forceinline__ void mma16816(float* c, const uint32_t* a, const uint32_t* b) {
    asm volatile("mma.sync.aligned.m16n8k16.row.col.f32.f16.f16.f32 "
        "{%0,%1,%2,%3}, {%4,%5,%6,%7}, {%8,%9}, {%0,%1,%2,%3};"
        : "+f"(c[0]), "+f"(c[1]), "+f"(c[2]), "+f"(c[3])
        : "r"(a[0]), "r"(a[1]), "r"(a[2]), "r"(a[3]), "r"(b[0]), "r"(b[1]));
}

__global__ void convert_kernel(const float* __restrict__ q, const float* __restrict__ k,
                               const float* __restrict__ v, int n4) {
    int i = blockIdx.x * blockDim.x + threadIdx.x;
    if (i >= n4) return;
    float4 a = reinterpret_cast<const float4*>(q)[i];
    float4 b = reinterpret_cast<const float4*>(k)[i];
    float4 c = reinterpret_cast<const float4*>(v)[i];
    __half2 h;
    uint2 u;
    h = __floats2half2_rn(a.x, a.y); u.x = *reinterpret_cast<uint32_t*>(&h);
    h = __floats2half2_rn(a.z, a.w); u.y = *reinterpret_cast<uint32_t*>(&h);
    reinterpret_cast<uint2*>(g_Qh)[i] = u;
    h = __floats2half2_rn(b.x, b.y); u.x = *reinterpret_cast<uint32_t*>(&h);
    h = __floats2half2_rn(b.z, b.w); u.y = *reinterpret_cast<uint32_t*>(&h);
    reinterpret_cast<uint2*>(g_Kh)[i] = u;
    h = __floats2half2_rn(c.x, c.y); u.x = *reinterpret_cast<uint32_t*>(&h);
    h = __floats2half2_rn(c.z, c.w); u.y = *reinterpret_cast<uint32_t*>(&h);
    reinterpret_cast<uint2*>(g_Vh)[i] = u;
}

// Load 64 keys of K (full 512 d) into the two K half-buffers.
__device__ __forceinline__ void load_k64(const __half* Kg, int tid, uint32_t kbuf) {
    #pragma unroll
    for (int i = tid; i < NKK * (DIM / 8); i += 256) {   // 16 per thread
        int r = i >> 6, c8 = i & 63;
        cp16(kbuf + (r >= 32 ? KBUF : 0) + km_off(r & 31, c8 * 8, 4),
             Kg + (size_t)r * DIM + c8 * 8);
    }
}
// Load 64 keys of V (256 d-cols) into the two V half-buffers.
__device__ __forceinline__ void load_v64(const __half* Vg, int tid, uint32_t vbuf) {
    #pragma unroll
    for (int i = tid; i < NKK * (DV / 8); i += 256) {    // 8 per thread
        int r = i >> 5, c8 = i & 31;
        cp16(vbuf + (r >= 32 ? VBUF : 0) + km_off(r & 31, c8 * 8, 4),
             Vg + (size_t)r * DIM + c8 * 8);
    }
}

// FlashAttention-2, mma.sync, 8 warps m-split, 64-key macro-iterations,
// staggered K/V prefetch. grid (8, BS, 2): q-tile pair {15-x, x} per CTA.
__global__ void __launch_bounds__(256, 1)
attn_kernel(const int* __restrict__ um_p, const int* __restrict__ cd_p,
            float* __restrict__ out) {
    extern __shared__ char smem[];
    const uint32_t sb = smem_u32(smem);
    const int tid = threadIdx.x, lane = tid & 31, w = tid >> 5;
    const int b = blockIdx.y, ds = blockIdx.z;
    const int dofs = ds * DV;
    const int um = um_p[0];
    const float cl2 = 1.4426950408889634f * rsqrtf((float)cd_p[0]);
    const float NEG = __int_as_float(0xff800000);

    const __half* Kg0 = g_Kh + ((size_t)(b * SEQ)) * DIM;
    const __half* Vg0 = g_Vh + ((size_t)(b * SEQ)) * DIM + dofs;

    const int arow = w * 16 + (lane & 15);
    const int acol = (lane >> 4) << 3;
    const int brow = lane & 7;
    const int bcol = ((lane >> 3) & 3) << 3;
    const int vrow = lane & 15;
    const int vcol = (lane >> 4) << 3;
    const int cofs = (lane & 3) << 1;

    #pragma unroll 1
    for (int ph = 0; ph < 2; ph++) {
        const int qi = ph ? (int)blockIdx.x : (NQT - 1) - (int)blockIdx.x; // heavy first
        const int q0 = qi * MQ;
        const int nkt = um ? (2 * qi + 2) : NKT;

        // ---- phase prologue: [Q + K(0)] group, [V(0)] group ----
        CP_WAIT0();
        __syncthreads();
        {
            const __half* Qg = g_Qh + ((size_t)(b * SEQ + q0)) * DIM;
            #pragma unroll 8
            for (int i = tid; i < MQ * (DIM / 8); i += 256) {
                int r = i >> 6, c8 = i & 63;
                cp16(sb + SM_Q + km_off(r, c8 * 8, 16), Qg + (size_t)r * DIM + c8 * 8);
            }
        }
        load_k64(Kg0, tid, sb + SM_K);
        CP_COMMIT();                                   // gK(0) (incl. Q)
        load_v64(Vg0, tid, sb + SM_V);
        CP_COMMIT();                                   // gV(0)

        float o[32][4];
        #pragma unroll
        for (int j = 0; j < 32; j++) { o[j][0] = 0.f; o[j][1] = 0.f; o[j][2] = 0.f; o[j][3] = 0.f; }
        float m0 = NEG, m1 = NEG, l0 = 0.f, l1 = 0.f;  // l kept lane-partial

        const int qrow0 = q0 + w * 16 + (lane >> 2);
        const int qrow1 = qrow0 + 8;

        for (int kt = 0; kt < nkt; kt++) {
            const int k0 = kt * NKK;

            CP_WAIT1();            // K(kt) (+Q) landed; V group may be in flight
            __syncthreads();

            // ---- S = Q K^T over 64 keys ----
            float s[8][4];
            #pragma unroll
            for (int nt = 0; nt < 8; nt++) { s[nt][0] = 0.f; s[nt][1] = 0.f; s[nt][2] = 0.f; s[nt][3] = 0.f; }
            #pragma unroll
            for (int kc2 = 0; kc2 < 16; kc2++) {
                uint32_t a0[4], a1[4];
                ldsm_x4(a0, sb + SM_Q + km_off(arow, kc2 * 32 + acol, 16));
                ldsm_x4(a1, sb + SM_Q + km_off(arow, kc2 * 32 + 16 + acol, 16));
                #pragma unroll
                for (int nt = 0; nt < 8; nt++) {
                    uint32_t bb[4];
                    ldsm_x4(bb, sb + SM_K + (nt >= 4 ? KBUF : 0)
                                + km_off((nt & 3) * 8 + brow, kc2 * 32 + bcol, 4));
                    mma16816(s[nt], a0, bb);
                    mma16816(s[nt], a1, bb + 2);
                }
            }

            // K halves fully consumed -> prefetch K(kt+1)
            __syncthreads();
            if (kt + 1 < nkt) load_k64(Kg0 + (size_t)(k0 + NKK) * DIM, tid, sb + SM_K);
            CP_COMMIT();                               // gK(kt+1)

            // ---- causal mask (diagonal macro-tiles only) ----
            if (um && kt >= 2 * qi) {
                #pragma unroll
                for (int nt = 0; nt < 8; nt++) {
                    int c = k0 + nt * 8 + cofs;
                    if (c     > qrow0) s[nt][0] = NEG;
                    if (c + 1 > qrow0) s[nt][1] = NEG;
                    if (c     > qrow1) s[nt][2] = NEG;
                    if (c + 1 > qrow1) s[nt][3] = NEG;
                }
            }

            // ---- online softmax (sums stay lane-partial) ----
            float vx0 = NEG, vx1 = NEG;
            #pragma unroll
            for (int nt = 0; nt < 8; nt++) {
                vx0 = fmaxf(vx0, fmaxf(s[nt][0], s[nt][1]));
                vx1 = fmaxf(vx1, fmaxf(s[nt][2], s[nt][3]));
            }
            vx0 = fmaxf(vx0, __shfl_xor_sync(0xffffffffu, vx0, 1));
            vx0 = fmaxf(vx0, __shfl_xor_sync(0xffffffffu, vx0, 2));
            vx1 = fmaxf(vx1, __shfl_xor_sync(0xffffffffu, vx1, 1));
            vx1 = fmaxf(vx1, __shfl_xor_sync(0xffffffffu, vx1, 2));
            const float nm0 = fmaxf(m0, vx0), nm1 = fmaxf(m1, vx1);

            float sum0 = 0.f, sum1 = 0.f;
            #pragma unroll
            for (int nt = 0; nt < 8; nt++) {
                s[nt][0] = ex2f((s[nt][0] - nm0) * cl2);
                s[nt][1] = ex2f((s[nt][1] - nm0) * cl2);
                s[nt][2] = ex2f((s[nt][2] - nm1) * cl2);
                s[nt][3] = ex2f((s[nt][3] - nm1) * cl2);
                sum0 += s[nt][0] + s[nt][1];
                sum1 += s[nt][2] + s[nt][3];
            }

            const bool rescale = (vx0 > m0) || (vx1 > m1);
            const float al0 = ex2f((m0 - nm0) * cl2), al1 = ex2f((m1 - nm1) * cl2);
            l0 = l0 * al0 + sum0;
            l1 = l1 * al1 + sum1;
            m0 = nm0; m1 = nm1;
            if (__any_sync(0xffffffffu, rescale)) {
                #pragma unroll
                for (int j = 0; j < 32; j++) {
                    o[j][0] *= al0; o[j][1] *= al0; o[j][2] *= al1; o[j][3] *= al1;
                }
            }

            CP_WAIT1();            // V(kt) landed; K(kt+1) may be in flight
            __syncthreads();

            // ---- O += P V  (two 32-key halves) ----
            #pragma unroll
            for (int h = 0; h < 2; h++) {
                const uint32_t vb = sb + SM_V + h * VBUF;
                uint32_t pa[2][4];
                #pragma unroll
                for (int kc = 0; kc < 2; kc++) {
                    const int nb = h * 4 + 2 * kc;
                    __half2 hh;
                    hh = __floats2half2_rn(s[nb][0],   s[nb][1]);   pa[kc][0] = *reinterpret_cast<uint32_t*>(&hh);
                    hh = __floats2half2_rn(s[nb][2],   s[nb][3]);   pa[kc][1] = *reinterpret_cast<uint32_t*>(&hh);
                    hh = __floats2half2_rn(s[nb+1][0], s[nb+1][1]); pa[kc][2] = *reinterpret_cast<uint32_t*>(&hh);
                    hh = __floats2half2_rn(s[nb+1][2], s[nb+1][3]); pa[kc][3] = *reinterpret_cast<uint32_t*>(&hh);
                }
                #pragma unroll
                for (int dt2 = 0; dt2 < 16; dt2++) {
                    #pragma unroll
                    for (int kc = 0; kc < 2; kc++) {
                        uint32_t bb[4];
                        ldsm_x4t(bb, vb + km_off(kc * 16 + vrow, dt2 * 16 + vcol, 4));
                        mma16816(o[2*dt2],     pa[kc], bb);
                        mma16816(o[2*dt2 + 1], pa[kc], bb + 2);
                    }
                }
            }

            // V halves consumed -> prefetch V(kt+1)
            __syncthreads();
            if (kt + 1 < nkt) load_v64(Vg0 + (size_t)(k0 + NKK) * DIM, tid, sb + SM_V);
            CP_COMMIT();                               // gV(kt+1)
        }

        // ---- phase epilogue (finish deferred l reduction) ----
        l0 += __shfl_xor_sync(0xffffffffu, l0, 1);
        l0 += __shfl_xor_sync(0xffffffffu, l0, 2);
        l1 += __shfl_xor_sync(0xffffffffu, l1, 1);
        l1 += __shfl_xor_sync(0xffffffffu, l1, 2);
        const float i0 = 1.f / l0, i1 = 1.f / l1;
        float* out0 = out + ((size_t)b * SEQ + qrow0) * DIM + dofs;
        float* out1 = out + ((size_t)b * SEQ + qrow1) * DIM + dofs;
        #pragma unroll
        for (int j = 0; j < 32; j++) {
            float2 v0 = make_float2(o[j][0] * i0, o[j][1] * i0);
            float2 v1 = make_float2(o[j][2] * i1, o[j][3] * i1);
            *reinterpret_cast<float2*>(out0 + j * 8 + cofs) = v0;
            *reinterpret_cast<float2*>(out1 + j * 8 + cofs) = v1;
        }
    }
}

extern "C" void kernel_launch(void* const* d_in, const int* in_sizes, int n_in,
                              void* d_out, int out_size) {
    const float* Q = (const float*)d_in[0];
    const float* K = (const float*)d_in[1];
    const float* V = (const float*)d_in[2];
    const int* use_mask = (const int*)d_in[3];
    const int* cell_dim = (const int*)d_in[4];
    float* out = (float*)d_out;

    int n4 = (BS * SEQ * DIM) / 4;
    convert_kernel<<<(n4 + 255) / 256, 256>>>(Q, K, V, n4);

    cudaFuncSetAttribute(attn_kernel, cudaFuncAttributeMaxDynamicSharedMemorySize, SM_TOTAL);
    attn_kernel<<<dim3(NQT / 2, BS, 2), 256, SM_TOTAL>>>(use_mask, cell_dim, out);
}